// round 7
// baseline (speedup 1.0000x reference)
#include <cuda_runtime.h>
#include <cuda_bf16.h>
#include <cstdint>

// HashEmbedding gather with bucket-level dedup.
// out[row,:] = embedding[hashed_ids[row],:], 32768 rows x 4096 B,
// ids in [0,10000). Avg multiplicity ~3.3.
//
// All previous variants (LDG.128/256, stcs, SW pipeline, TMA chunks)
// converge at 27-29us because LTS traffic = 134MB reads + 134MB writes.
// R7 inverts the map (bucket -> rows) so each table row crosses LTS
// ONCE: 40MB reads + 134MB writes.
//
//   K1: zero per-bucket counters
//   K2: scatter row indices into per-bucket slot lists (atomicAdd)
//   K3: warp per bucket: TMA bulk-load the 4KB row into SMEM once,
//       then lane i bulk-stores it to output row slots[b][i].
// Processing order varies with atomics, but out[row] depends only on
// emb[id] -> output is deterministic.

static constexpr int NUM_BUCKETS = 10000;
static constexpr int CAP         = 64;      // max rows per bucket (avg 3.3, Poisson-safe)
static constexpr int ROW_BYTES   = 4096;
static constexpr int WARPS       = 8;       // buckets per CTA in K3
static constexpr int K3_SMEM     = 1024 + WARPS * ROW_BYTES;   // mbars + stages

__device__ int g_counts[NUM_BUCKETS];
__device__ int g_slots[NUM_BUCKETS * CAP];

// ---------- PTX helpers ----------
__device__ __forceinline__ uint32_t smem_u32(const void* p)
{
    uint32_t a;
    asm("{ .reg .u64 t; cvta.to.shared.u64 t, %1; cvt.u32.u64 %0, t; }"
        : "=r"(a) : "l"(p));
    return a;
}

__device__ __forceinline__ void mbar_init(uint32_t mbar, uint32_t count)
{
    asm volatile("mbarrier.init.shared.b64 [%0], %1;" :: "r"(mbar), "r"(count) : "memory");
}

__device__ __forceinline__ void mbar_expect_tx(uint32_t mbar, uint32_t bytes)
{
    asm volatile("mbarrier.arrive.expect_tx.shared.b64 _, [%0], %1;"
                 :: "r"(mbar), "r"(bytes) : "memory");
}

__device__ __forceinline__ void mbar_wait(uint32_t mbar, uint32_t parity)
{
    asm volatile(
        "{\n\t"
        ".reg .pred P;\n\t"
        "W_%=:\n\t"
        "mbarrier.try_wait.parity.shared.b64 P, [%0], %1, 0x989680;\n\t"
        "@P bra.uni D_%=;\n\t"
        "bra.uni W_%=;\n\t"
        "D_%=:\n\t"
        "}"
        :: "r"(mbar), "r"(parity) : "memory");
}

__device__ __forceinline__ void bulk_load(uint32_t dst_smem, const void* src,
                                          uint32_t bytes, uint32_t mbar)
{
    asm volatile(
        "cp.async.bulk.shared::cta.global.mbarrier::complete_tx::bytes "
        "[%0], [%1], %2, [%3];"
        :: "r"(dst_smem), "l"(src), "r"(bytes), "r"(mbar) : "memory");
}

__device__ __forceinline__ void bulk_store(void* dst, uint32_t src_smem,
                                           uint32_t bytes)
{
    asm volatile(
        "cp.async.bulk.global.shared::cta.bulk_group [%0], [%1], %2;"
        :: "l"(dst), "r"(src_smem), "r"(bytes) : "memory");
}

__device__ __forceinline__ void store_commit()
{
    asm volatile("cp.async.bulk.commit_group;" ::: "memory");
}

__device__ __forceinline__ void store_wait_all()
{
    asm volatile("cp.async.bulk.wait_group 0;" ::: "memory");
}

__device__ __forceinline__ void fence_async()
{
    asm volatile("fence.proxy.async.shared::cta;" ::: "memory");
}

// ---------- K1: zero counters ----------
__global__ void __launch_bounds__(256)
k_zero()
{
    int i = blockIdx.x * 256 + threadIdx.x;
    if (i < NUM_BUCKETS) g_counts[i] = 0;
}

// ---------- K2: build bucket -> row lists ----------
__global__ void __launch_bounds__(256)
k_scatter(const int* __restrict__ hashed_ids, int nrows)
{
    int i = blockIdx.x * 256 + threadIdx.x;
    if (i >= nrows) return;
    int id  = __ldg(hashed_ids + i);
    int pos = atomicAdd(&g_counts[id], 1);
    if (pos < CAP) g_slots[id * CAP + pos] = i;
}

// ---------- K3: dedup gather: 1 read per bucket, fan-out stores ----------
__global__ void __launch_bounds__(32 * WARPS)
k_gather(const char* __restrict__ emb, char* __restrict__ out)
{
    extern __shared__ char smem[];
    const uint32_t base = smem_u32(smem);

    const int wid  = threadIdx.x >> 5;
    const int lane = threadIdx.x & 31;
    const int b    = blockIdx.x * WARPS + wid;
    if (b >= NUM_BUCKETS) return;

    const int cnt = __ldg(&g_counts[b]);   // same addr across warp: 1 request
    if (cnt == 0) return;

    const uint32_t mbar  = base + wid * 8;
    const uint32_t stage = base + 1024 + wid * ROW_BYTES;

    if (lane == 0) {
        mbar_init(mbar, 1);
        fence_async();
        mbar_expect_tx(mbar, ROW_BYTES);
        bulk_load(stage, emb + (size_t)b * ROW_BYTES, ROW_BYTES, mbar);
    }
    __syncwarp();

    // Each lane fetches its output-row index while the row load flies.
    int row0 = -1, row1 = -1;
    if (lane < cnt)           row0 = __ldg(&g_slots[b * CAP + lane]);
    if (lane + 32 < cnt)      row1 = __ldg(&g_slots[b * CAP + lane + 32]);

    mbar_wait(mbar, 0);
    fence_async();

    // Fan-out: each lane issues an independent 4KB bulk store.
    bool issued = false;
    if (row0 >= 0) { bulk_store(out + (size_t)row0 * ROW_BYTES, stage, ROW_BYTES); issued = true; }
    if (row1 >= 0) { bulk_store(out + (size_t)row1 * ROW_BYTES, stage, ROW_BYTES); issued = true; }
    if (issued) {
        store_commit();
        store_wait_all();      // SMEM must stay valid until stores complete
    }
}

// ---------- launch ----------
extern "C" void kernel_launch(void* const* d_in, const int* in_sizes, int n_in,
                              void* d_out, int out_size)
{
    // metadata order: input_ids (unused), hashed_ids (int32), embedding (fp32)
    const int*  hashed_ids = (const int*)d_in[1];
    const char* emb        = (const char*)d_in[2];
    char*       out        = (char*)d_out;

    int nrows = in_sizes[1];   // 32768

    k_zero<<<(NUM_BUCKETS + 255) / 256, 256>>>();
    k_scatter<<<(nrows + 255) / 256, 256>>>(hashed_ids, nrows);
    k_gather<<<(NUM_BUCKETS + WARPS - 1) / WARPS, 32 * WARPS, K3_SMEM>>>(emb, out);
}

// round 8
// speedup vs baseline: 1.2884x; 1.2884x over previous
#include <cuda_runtime.h>
#include <cuda_bf16.h>
#include <cstdint>

// HashEmbedding gather: out[row,:] = embedding[hashed_ids[row],:]
// rows = 32768, D = 1024 fp32 = 256 float4 per row.
//
// R8: best-measured config (R2: float4 + __stcs streaming stores,
// kernel 27.2us) plus R3's untested deltas: int2 id fetch amortization
// and MLP=8 front-batched gathers (2 rows per 64-lane sub-group).
// DRAM traffic is a pure 134MB write stream (~4.7 TB/s write ceiling);
// this is at/near the floor, so only micro-gains expected.

static constexpr int D_F4 = 256;          // float4 per row
static constexpr int THREADS = 256;
static constexpr int LANES = 64;          // threads per row
static constexpr int ROWS_PER_BLK = 8;    // 4 sub-groups x 2 rows

__global__ void __launch_bounds__(THREADS)
hash_embedding_gather(const int* __restrict__ hashed_ids,
                      const float4* __restrict__ emb,
                      float4* __restrict__ out,
                      int nrows)
{
    int t    = threadIdx.x;
    int sub  = t >> 6;        // 0..3
    int lane = t & 63;        // 0..63

    int row0 = blockIdx.x * ROWS_PER_BLK + sub * 2;
    if (row0 >= nrows) return;

    // One 8-byte load fetches both ids (row0 even -> 8B aligned).
    int2 ids = *reinterpret_cast<const int2*>(hashed_ids + row0);

    const float4* __restrict__ srcA = emb + (size_t)ids.x * D_F4;
    const float4* __restrict__ srcB = emb + (size_t)ids.y * D_F4;
    float4*       __restrict__ dstA = out + (size_t)row0       * D_F4;
    float4*       __restrict__ dstB = out + (size_t)(row0 + 1) * D_F4;

    // 8 independent gathers, front-batched (MLP=8 per thread).
    float4 a0 = __ldg(srcA + lane);
    float4 a1 = __ldg(srcA + lane + LANES);
    float4 a2 = __ldg(srcA + lane + 2 * LANES);
    float4 a3 = __ldg(srcA + lane + 3 * LANES);
    float4 b0 = __ldg(srcB + lane);
    float4 b1 = __ldg(srcB + lane + LANES);
    float4 b2 = __ldg(srcB + lane + 2 * LANES);
    float4 b3 = __ldg(srcB + lane + 3 * LANES);

    // Streaming stores (evict-first): output is write-once; keeps the
    // 40MB table resident in L2. Measured faster in R2.
    __stcs(dstA + lane,             a0);
    __stcs(dstA + lane + LANES,     a1);
    __stcs(dstA + lane + 2 * LANES, a2);
    __stcs(dstA + lane + 3 * LANES, a3);
    __stcs(dstB + lane,             b0);
    __stcs(dstB + lane + LANES,     b1);
    __stcs(dstB + lane + 2 * LANES, b2);
    __stcs(dstB + lane + 3 * LANES, b3);
}

extern "C" void kernel_launch(void* const* d_in, const int* in_sizes, int n_in,
                              void* d_out, int out_size)
{
    // metadata order: input_ids (unused), hashed_ids (int32), embedding (fp32)
    const int*    hashed_ids = (const int*)d_in[1];
    const float4* emb        = (const float4*)d_in[2];
    float4*       out        = (float4*)d_out;

    int nrows = in_sizes[1];   // 32768
    int blocks = (nrows + ROWS_PER_BLK - 1) / ROWS_PER_BLK;

    hash_embedding_gather<<<blocks, THREADS>>>(hashed_ids, emb, out, nrows);
}